// round 16
// baseline (speedup 1.0000x reference)
#include <cuda_runtime.h>
#include <math.h>
#include <stdint.h>

// ---------------- device scratch ----------------
__device__ __align__(16) float g_trel[500 * 100];
__device__ __align__(16) float g_tin[8192 * 500];
__device__ __align__(16) float g_xp[8192 * 1024];
__device__ __align__(16) float g_outseq[8192 * 256];

// ---------------- helpers ----------------
__device__ __forceinline__ unsigned smem_u32(const void* p) {
    return (unsigned)__cvta_generic_to_shared(p);
}
__device__ __forceinline__ void cpa16(unsigned dst, const void* src) {
    asm volatile("cp.async.cg.shared.global [%0], [%1], 16;\n" :: "r"(dst), "l"(src));
}
#define CPA_COMMIT() asm volatile("cp.async.commit_group;\n")
template <int N> __device__ __forceinline__ void cpa_wait() {
    asm volatile("cp.async.wait_group %0;\n" :: "n"(N));
}
#define FMA2(acc, h, w) \
    asm("fma.rn.f32x2 %0, %1, %2, %0;" : "+l"(acc) : "l"(h), "l"(w))
#define UNPACK2(lo, hi, src) \
    asm("mov.b64 {%0, %1}, %2;" : "=f"(lo), "=f"(hi) : "l"(src))
#define PACKF2(dst, a, b) \
    asm("mov.b64 %0, {%1, %2};" : "=l"(dst) : "f"(a), "f"(b))
#define CLUSTER_ARRIVE() asm volatile("barrier.cluster.arrive.aligned;" ::: "memory")
#define CLUSTER_WAIT()   asm volatile("barrier.cluster.wait.aligned;" ::: "memory")

__device__ __forceinline__ float fast_sigmoid(float x) {
    return __fdividef(1.f, 1.f + __expf(-x));
}
__device__ __forceinline__ float fast_tanh(float x) {
    float e = __expf(2.f * x);
    return 1.f - __fdividef(2.f, e + 1.f);
}
__device__ __forceinline__ uint32_t f2tf(float x) {
    uint32_t r;
    asm("cvt.rna.tf32.f32 %0, %1;" : "=r"(r) : "f"(x));
    return r;
}
#define MMA_TF32(c, a, b) \
    asm volatile("mma.sync.aligned.m16n8k8.row.col.f32.tf32.tf32.f32 " \
        "{%0,%1,%2,%3}, {%4,%5,%6,%7}, {%8,%9}, {%0,%1,%2,%3};" \
        : "+f"((c)[0]), "+f"((c)[1]), "+f"((c)[2]), "+f"((c)[3]) \
        : "r"((a)[0]), "r"((a)[1]), "r"((a)[2]), "r"((a)[3]), \
          "r"((b)[0]), "r"((b)[1]))

// ============================================================================
// K0: precompute tanh(rel_emb)
// ============================================================================
__global__ void k_tanh_rel(const float* __restrict__ rel) {
    int i = blockIdx.x * 256 + threadIdx.x;
    if (i < 500 * 100) g_trel[i] = tanhf(rel[i]);
}

// ============================================================================
// K1: graph attention v4. 148 CTAs x 512 threads, 56 tokens per CTA.
// DEPTH-4 cp.async pipeline. 7 MMA warps x (m32 n16 k200) tf32.
// smem floats (FIXED layout — sIdx is 56*96 = 5376 ints):
//   sW    100*204 = 20400  @ 0
//   sHT   4*32*204 = 26112 @ 20400
//   sE    32               @ 46512
//   sPART 256              @ 46544
//   sIdx  5376 ints        @ 46800
//   sVal  56 ints          @ 52176
// total 52232 floats = 208928 B  (< 227 KB cap)
// ============================================================================
#define TPC       56
#define TOK_SW    0
#define TOK_SHT   20400
#define TOK_SE    46512
#define TOK_SPART 46544
#define TOK_SIDX  46800
#define TOK_SVAL  52176
#define TOK_SMEM  (52232 * 4)

__device__ __forceinline__ void tok_stage(float* sm, int buf, int it,
                                          const float* ent_emb, bool valid) {
    if (!valid) return;
    const int* idx = (const int*)(sm + TOK_SIDX) + it * 96;
    float* sHT = sm + TOK_SHT + buf * 32 * 204;
    for (int i = threadIdx.x; i < 1600; i += 512) {
        int t = i / 50, j = i - t * 50;
        int ent = (j < 25) ? idx[t * 3] : idx[t * 3 + 1];
        int jj = (j < 25) ? j : (j - 25);
        int dstf = t * 204 + ((j < 25) ? (j * 4) : (100 + jj * 4));
        cpa16(smem_u32(sHT + dstf), ent_emb + (size_t)ent * 100 + jj * 4);
    }
}

__global__ void __launch_bounds__(512, 1)
k_token(const int* __restrict__ inputs, const int* __restrict__ triples,
        const int* __restrict__ id2, const float* __restrict__ word_emb,
        const float* __restrict__ ent_emb, const float* __restrict__ W_ent)
{
    extern __shared__ float sm[];
    const int tid = threadIdx.x;
    const int tok0 = blockIdx.x * TPC;
    int* sIdx = (int*)(sm + TOK_SIDX);
    int* sVal = (int*)(sm + TOK_SVAL);

    // prologue: indices for 56 tokens (1344 cp16 = 5376 ints) + W_ent
    for (int i = tid; i < 1344; i += 512) {
        if (tok0 + i / 24 < 8192)
            cpa16(smem_u32(sIdx) + i * 16, triples + (size_t)tok0 * 96 + i * 4);
    }
    for (int i = tid; i < 5000; i += 512) {
        int d = i / 50, j = i - d * 50;
        cpa16(smem_u32(sm + TOK_SW + d * 204 + j * 4), W_ent + d * 200 + j * 4);
    }
    CPA_COMMIT();
    cpa_wait<0>();
    __syncthreads();

    // convert sW to tf32 bit patterns (reused 56 tokens)
    for (int i = tid; i < 20000; i += 512) {
        int d = i / 200, j = i - d * 200;
        ((uint32_t*)sm)[TOK_SW + d * 204 + j] = f2tf(sm[TOK_SW + d * 204 + j]);
    }

    // per-token valid flags
    {
        int w = tid >> 5, lane = tid & 31;
        for (int it = w; it < TPC; it += 16) {
            int token = tok0 + it;
            int v = (token < 8192) ? id2[(size_t)token * 32 + lane] : -1;
            unsigned m = __ballot_sync(0xffffffffu, v != -1);
            if (lane == 0) sVal[it] = (m != 0u);
        }
    }
    __syncthreads();

    // prime pipeline: stages 0,1,2 (3 groups in flight)
    tok_stage(sm, 0, 0, ent_emb, tok0 + 0 < 8192); CPA_COMMIT();
    tok_stage(sm, 1, 1, ent_emb, tok0 + 1 < 8192); CPA_COMMIT();
    tok_stage(sm, 2, 2, ent_emb, tok0 + 2 < 8192); CPA_COMMIT();

    const int warp = tid >> 5;
    const int lane = tid & 31;
    const int g  = lane >> 2;        // 0..7
    const int tg = lane & 3;         // 0..3

    for (int it = 0; it < TPC; ++it) {
        const int buf = it & 3;
        if (it + 3 < TPC) {
            tok_stage(sm, (it + 3) & 3, it + 3, ent_emb, tok0 + it + 3 < 8192);
            CPA_COMMIT();
        }
        {
            int rem = TPC - 1 - it;
            if (rem >= 3)      cpa_wait<3>();
            else if (rem == 2) cpa_wait<2>();
            else if (rem == 1) cpa_wait<1>();
            else               cpa_wait<0>();
        }
        __syncthreads();

        const int token = tok0 + it;
        const bool tv = (token < 8192);
        const float* sHT = sm + TOK_SHT + buf * 32 * 204;

        if (tv && warp < 7) {
            // prefetch trel (hidden under MMA)
            const int* idx = sIdx + it * 96;
            int c0 = warp * 16 + tg * 2;
            int cols[4] = {c0, c0 + 1, c0 + 8, c0 + 9};
            float T[4][4];
            #pragma unroll
            for (int rr = 0; rr < 4; ++rr) {
                int rl = idx[(g + rr * 8) * 3 + 2];
                #pragma unroll
                for (int cc = 0; cc < 4; ++cc)
                    T[rr][cc] = (cols[cc] < 100) ? __ldg(g_trel + rl * 100 + cols[cc]) : 0.f;
            }

            float acc[2][2][4];
            #pragma unroll
            for (int mt = 0; mt < 2; ++mt)
                #pragma unroll
                for (int nt = 0; nt < 2; ++nt)
                    #pragma unroll
                    for (int c = 0; c < 4; ++c) acc[mt][nt][c] = 0.f;

            const float* Afrag = sHT + g * 204 + tg;
            const uint32_t* B0 = (const uint32_t*)(sm + TOK_SW) + (warp * 16 + g) * 204 + tg;
            const uint32_t* B1 = (const uint32_t*)(sm + TOK_SW) + (warp * 16 + 8 + g) * 204 + tg;
            const bool okn0 = (warp * 16 + g) < 100;
            const bool okn1 = (warp * 16 + 8 + g) < 100;

            #pragma unroll 5
            for (int ks = 0; ks < 25; ++ks) {
                int ko = ks * 8;
                uint32_t a[2][4], b0[2], b1[2];
                #pragma unroll
                for (int mt = 0; mt < 2; ++mt) {
                    const float* p = Afrag + mt * (16 * 204) + ko;
                    a[mt][0] = f2tf(p[0]);
                    a[mt][1] = f2tf(p[8 * 204]);
                    a[mt][2] = f2tf(p[4]);
                    a[mt][3] = f2tf(p[8 * 204 + 4]);
                }
                b0[0] = okn0 ? B0[ko] : 0u;  b0[1] = okn0 ? B0[ko + 4] : 0u;
                b1[0] = okn1 ? B1[ko] : 0u;  b1[1] = okn1 ? B1[ko + 4] : 0u;
                MMA_TF32(acc[0][0], a[0], b0);
                MMA_TF32(acc[0][1], a[0], b1);
                MMA_TF32(acc[1][0], a[1], b0);
                MMA_TF32(acc[1][1], a[1], b1);
            }

            float pr[4];
            pr[0] = fast_tanh(acc[0][0][0]) * T[0][0] + fast_tanh(acc[0][0][1]) * T[0][1]
                  + fast_tanh(acc[0][1][0]) * T[0][2] + fast_tanh(acc[0][1][1]) * T[0][3];
            pr[1] = fast_tanh(acc[0][0][2]) * T[1][0] + fast_tanh(acc[0][0][3]) * T[1][1]
                  + fast_tanh(acc[0][1][2]) * T[1][2] + fast_tanh(acc[0][1][3]) * T[1][3];
            pr[2] = fast_tanh(acc[1][0][0]) * T[2][0] + fast_tanh(acc[1][0][1]) * T[2][1]
                  + fast_tanh(acc[1][1][0]) * T[2][2] + fast_tanh(acc[1][1][1]) * T[2][3];
            pr[3] = fast_tanh(acc[1][0][2]) * T[3][0] + fast_tanh(acc[1][0][3]) * T[3][1]
                  + fast_tanh(acc[1][1][2]) * T[3][2] + fast_tanh(acc[1][1][3]) * T[3][3];
            #pragma unroll
            for (int rr = 0; rr < 4; ++rr) {
                pr[rr] += __shfl_xor_sync(0xffffffffu, pr[rr], 1);
                pr[rr] += __shfl_xor_sync(0xffffffffu, pr[rr], 2);
            }
            if (tg == 0) {
                #pragma unroll
                for (int rr = 0; rr < 4; ++rr)
                    sm[TOK_SPART + (g + rr * 8) * 8 + warp] = pr[rr];
            }
        } else if (tv && warp >= 7) {
            const int widx = inputs[token];
            const float2* wsrc = (const float2*)(word_emb + (size_t)widx * 300);
            float2* wdst = (float2*)(g_tin + (size_t)token * 500);
            for (int j = tid - 224; j < 150; j += 288) wdst[j] = wsrc[j];
        }
        __syncthreads();

        if (tv && tid < 256) {          // reduce 7 warp-partials per row
            int t = tid >> 3, l = tid & 7;
            float v = (l < 7) ? sm[TOK_SPART + t * 8 + l] : 0.f;
            v += __shfl_xor_sync(0xffffffffu, v, 4);
            v += __shfl_xor_sync(0xffffffffu, v, 2);
            v += __shfl_xor_sync(0xffffffffu, v, 1);
            if (l == 0) sm[TOK_SE + t] = v;
        }
        __syncthreads();

        if (tv && tid < 32) {           // softmax over 32 triples
            float v = sm[TOK_SE + tid];
            float m = v;
            #pragma unroll
            for (int o = 16; o; o >>= 1) m = fmaxf(m, __shfl_xor_sync(0xffffffffu, m, o));
            float e = __expf(v - m);
            float z = e;
            #pragma unroll
            for (int o = 16; o; o >>= 1) z += __shfl_xor_sync(0xffffffffu, z, o);
            sm[TOK_SE + tid] = e / z;
        }
        __syncthreads();

        if (tv && tid < 200) {          // graph embed
            float ge = 0.f;
            #pragma unroll 8
            for (int t = 0; t < 32; ++t) ge += sm[TOK_SE + t] * sHT[t * 204 + tid];
            g_tin[(size_t)token * 500 + 300 + tid] = sVal[it] ? ge : 0.f;
        }
        __syncthreads();
    }
}

// ============================================================================
// K2: tf32 tensor-core GEMM (round-10 proven, FROZEN).
// ============================================================================
__global__ void __launch_bounds__(256)
k_mma_x(const float* __restrict__ wih, const float* __restrict__ bih,
        const float* __restrict__ bhh)
{
    __shared__ float As[128 * 36];
    __shared__ float Bs[64 * 36];

    const int tid  = threadIdx.x;
    const int lane = tid & 31;
    const int warp = tid >> 5;
    const int wm = warp >> 1;
    const int wn = warp & 1;
    const int g  = lane >> 2;
    const int tg = lane & 3;
    const int m0 = blockIdx.y * 128;
    const int n0 = blockIdx.x * 64;

    const int arow_i = tid >> 1;
    const int ahalf  = (tid & 1) * 16;
    const float* arow = g_tin + (size_t)(m0 + arow_i) * 500;
    const int brow_i = tid >> 2;
    const int bq     = (tid & 3) * 8;
    const float* brow = wih + (size_t)(n0 + brow_i) * 500;

    float acc[2][4][4];
    #pragma unroll
    for (int mt = 0; mt < 2; ++mt)
        #pragma unroll
        for (int nt = 0; nt < 4; ++nt)
            #pragma unroll
            for (int c = 0; c < 4; ++c) acc[mt][nt][c] = 0.f;

    float4 av[4], bv[2];
    #pragma unroll
    for (int j = 0; j < 4; ++j) {
        int k = ahalf + j * 4;
        av[j] = (k < 500) ? *(const float4*)(arow + k) : make_float4(0.f,0.f,0.f,0.f);
    }
    #pragma unroll
    for (int j = 0; j < 2; ++j) {
        int k = bq + j * 4;
        bv[j] = (k < 500) ? *(const float4*)(brow + k) : make_float4(0.f,0.f,0.f,0.f);
    }

    const float* Afrag = As + (wm * 32 + g) * 36 + tg;
    const float* Bfrag = Bs + (wn * 32 + g) * 36 + tg;

    for (int kt = 0; kt < 16; ++kt) {
        #pragma unroll
        for (int j = 0; j < 4; ++j)
            *(float4*)&As[arow_i * 36 + ahalf + j * 4] = av[j];
        #pragma unroll
        for (int j = 0; j < 2; ++j)
            *(float4*)&Bs[brow_i * 36 + bq + j * 4] = bv[j];
        __syncthreads();

        if (kt < 15) {
            int kb = (kt + 1) * 32;
            #pragma unroll
            for (int j = 0; j < 4; ++j) {
                int k = kb + ahalf + j * 4;
                av[j] = (k < 500) ? *(const float4*)(arow + k) : make_float4(0.f,0.f,0.f,0.f);
            }
            #pragma unroll
            for (int j = 0; j < 2; ++j) {
                int k = kb + bq + j * 4;
                bv[j] = (k < 500) ? *(const float4*)(brow + k) : make_float4(0.f,0.f,0.f,0.f);
            }
        }

        #pragma unroll
        for (int k8 = 0; k8 < 4; ++k8) {
            int ko = k8 * 8;
            uint32_t a[2][4], b[4][2];
            #pragma unroll
            for (int mt = 0; mt < 2; ++mt) {
                const float* p = Afrag + mt * (16 * 36) + ko;
                a[mt][0] = f2tf(p[0]);
                a[mt][1] = f2tf(p[8 * 36]);
                a[mt][2] = f2tf(p[4]);
                a[mt][3] = f2tf(p[8 * 36 + 4]);
            }
            #pragma unroll
            for (int nt = 0; nt < 4; ++nt) {
                const float* q = Bfrag + nt * (8 * 36) + ko;
                b[nt][0] = f2tf(q[0]);
                b[nt][1] = f2tf(q[4]);
            }
            #pragma unroll
            for (int mt = 0; mt < 2; ++mt)
                #pragma unroll
                for (int nt = 0; nt < 4; ++nt)
                    MMA_TF32(acc[mt][nt], a[mt], b[nt]);
        }
        __syncthreads();
    }

    #pragma unroll
    for (int nt = 0; nt < 4; ++nt) {
        int c = n0 + wn * 32 + nt * 8 + tg * 2;
        float b0 = bih[c] + bhh[c];
        float b1 = bih[c + 1] + bhh[c + 1];
        #pragma unroll
        for (int mt = 0; mt < 2; ++mt) {
            int r = m0 + wm * 32 + mt * 16 + g;
            float2 o0 = make_float2(acc[mt][nt][0] + b0, acc[mt][nt][1] + b1);
            float2 o1 = make_float2(acc[mt][nt][2] + b0, acc[mt][nt][3] + b1);
            *(float2*)(g_xp + (size_t)r * 1024 + c) = o0;
            *(float2*)(g_xp + (size_t)(r + 8) * 1024 + c) = o1;
        }
    }
}

// ============================================================================
// K3: cluster LSTM (round-8 design, FROZEN). 16 clusters x 8 CTAs x 256 thr.
// ============================================================================
__global__ void __launch_bounds__(256, 1) __cluster_dims__(8, 1, 1)
k_lstm(const float* __restrict__ whh, const int* __restrict__ lengths)
{
    __shared__ __align__(16) float sH[2][4][256];   // [buf][batch][k swizzled]

    const int tid  = threadIdx.x;
    const int rank = blockIdx.x & 7;
    const int cid  = blockIdx.x >> 3;
    const int b0g  = cid * 4;

    const int hc_l = tid >> 3;          // 0..31
    const int ks   = tid & 7;           // k-slice
    const int k_g  = rank * 32 + hc_l;

    unsigned long long w[4][16];
    #pragma unroll
    for (int g = 0; g < 4; ++g) {
        const float4* p = (const float4*)(whh + ((size_t)(g * 256 + k_g)) * 256 + ks * 32);
        #pragma unroll
        for (int j = 0; j < 8; ++j) {
            float4 v = __ldg(p + j);
            PACKF2(w[g][2*j],   v.x, v.y);
            PACKF2(w[g][2*j+1], v.z, v.w);
        }
    }

    for (int i = tid; i < 2 * 4 * 256; i += 256) (&sH[0][0][0])[i] = 0.f;

    const int ab = ks;                  // batch for activation lanes (ks<4)
    float cst = 0.f;
    int mylen = 0;
    if (ks < 4) mylen = lengths[b0g + ab];
    const int sw_idx = k_g ^ (rank << 2);

    __syncthreads();
    CLUSTER_ARRIVE(); CLUSTER_WAIT();

    int buf = 0;
    for (int s = 0; s < 128; ++s) {
        float xg0 = 0.f, xg1 = 0.f, xg2 = 0.f, xg3 = 0.f;
        if (ks < 4) {
            const float* xp = g_xp + ((size_t)((b0g + ab) * 128 + s)) * 1024 + k_g;
            xg0 = __ldg(xp);       xg1 = __ldg(xp + 256);
            xg2 = __ldg(xp + 512); xg3 = __ldg(xp + 768);
        }

        unsigned long long acc[4][4];
        #pragma unroll
        for (int g = 0; g < 4; ++g)
            #pragma unroll
            for (int b = 0; b < 4; ++b) acc[g][b] = 0ull;

        const float* hb = &sH[buf][0][0];
        #pragma unroll
        for (int i = 0; i < 8; ++i) {
            int off = (ks * 32 + i * 4) ^ (ks << 2);
            ulonglong2 x0 = *(const ulonglong2*)(hb + 0   + off);
            ulonglong2 x1 = *(const ulonglong2*)(hb + 256 + off);
            ulonglong2 x2 = *(const ulonglong2*)(hb + 512 + off);
            ulonglong2 x3 = *(const ulonglong2*)(hb + 768 + off);
            #pragma unroll
            for (int g = 0; g < 4; ++g) {
                FMA2(acc[g][0], x0.x, w[g][2*i]); FMA2(acc[g][0], x0.y, w[g][2*i+1]);
                FMA2(acc[g][1], x1.x, w[g][2*i]); FMA2(acc[g][1], x1.y, w[g][2*i+1]);
                FMA2(acc[g][2], x2.x, w[g][2*i]); FMA2(acc[g][2], x2.y, w[g][2*i+1]);
                FMA2(acc[g][3], x3.x, w[g][2*i]); FMA2(acc[g][3], x3.y, w[g][2*i+1]);
            }
        }

        float r[4][4];
        #pragma unroll
        for (int g = 0; g < 4; ++g)
            #pragma unroll
            for (int b = 0; b < 4; ++b) {
                float lo, hi;
                UNPACK2(lo, hi, acc[g][b]);
                r[g][b] = lo + hi;
            }
        #pragma unroll
        for (int o = 1; o < 8; o <<= 1)
            #pragma unroll
            for (int g = 0; g < 4; ++g)
                #pragma unroll
                for (int b = 0; b < 4; ++b)
                    r[g][b] += __shfl_xor_sync(0xffffffffu, r[g][b], o);

        if (ks < 4) {
            float gi = xg0 + r[0][ab];
            float gf = xg1 + r[1][ab];
            float gg = xg2 + r[2][ab];
            float go = xg3 + r[3][ab];
            float si = fast_sigmoid(gi);
            float sf = fast_sigmoid(gf);
            float so = fast_sigmoid(go);
            cst = sf * cst + si * fast_tanh(gg);
            float hv = so * fast_tanh(cst);
            g_outseq[((size_t)((b0g + ab) * 128 + s)) * 256 + k_g] =
                (s < mylen) ? hv : 0.f;
            unsigned laddr = smem_u32(&sH[buf ^ 1][ab][sw_idx]);
            #pragma unroll
            for (int rr = 0; rr < 8; ++rr) {
                unsigned raddr;
                asm("mapa.shared::cluster.u32 %0, %1, %2;" : "=r"(raddr) : "r"(laddr), "r"(rr));
                asm volatile("st.shared::cluster.f32 [%0], %1;" :: "r"(raddr), "f"(hv));
            }
        }
        CLUSTER_ARRIVE();
        CLUSTER_WAIT();
        buf ^= 1;
    }
}

// ============================================================================
// K4: attention pool + classifier (float4 dots, 16B-aligned shared).
// out = [ log_probs (64*3) | p (64*128) ]
// ============================================================================
__global__ void __launch_bounds__(256)
k_final(const float* __restrict__ W_att, const float* __restrict__ b_att,
        const float* __restrict__ W_out, const float* __restrict__ b_out,
        float* __restrict__ out)
{
    __shared__ __align__(16) float sLog[128];
    __shared__ __align__(16) float sP[128];
    __shared__ __align__(16) float sEnc[256];
    __shared__ __align__(16) float sZ[4];
    const int tid = threadIdx.x;
    const int b = blockIdx.x;

    if (tid < 128) {
        const float4* o = (const float4*)(g_outseq + (size_t)(b * 128 + tid) * 256);
        const float4* wv = (const float4*)W_att;
        float a = 0.f;
        #pragma unroll 8
        for (int h = 0; h < 64; ++h) {
            float4 ov = o[h], w4 = wv[h];
            a += ov.x * w4.x + ov.y * w4.y + ov.z * w4.z + ov.w * w4.w;
        }
        sLog[tid] = a + b_att[0];
    }
    __syncthreads();

    if (tid < 32) {
        float lv[4], mk[4];
        #pragma unroll
        for (int i = 0; i < 4; ++i) {
            float x = sLog[tid + 32 * i];
            mk[i] = (x != 0.f) ? 1.f : 0.f;
            lv[i] = x * mk[i];
        }
        float mx = fmaxf(fmaxf(lv[0], lv[1]), fmaxf(lv[2], lv[3]));
        #pragma unroll
        for (int o = 16; o; o >>= 1) mx = fmaxf(mx, __shfl_xor_sync(0xffffffffu, mx, o));
        float e[4], den = 0.f;
        #pragma unroll
        for (int i = 0; i < 4; ++i) { e[i] = __expf(lv[i] - mx); den += e[i]; }
        #pragma unroll
        for (int o = 16; o; o >>= 1) den += __shfl_xor_sync(0xffffffffu, den, o);
        float pv[4], s2 = 0.f;
        #pragma unroll
        for (int i = 0; i < 4; ++i) { pv[i] = e[i] / den * mk[i]; s2 += pv[i]; }
        #pragma unroll
        for (int o = 16; o; o >>= 1) s2 += __shfl_xor_sync(0xffffffffu, s2, o);
        float inv = 1.f / (s2 + 1e-13f);
        #pragma unroll
        for (int i = 0; i < 4; ++i) sP[tid + 32 * i] = pv[i] * inv;
    }
    __syncthreads();

    {
        float a = 0.f;
        const float* base = g_outseq + (size_t)b * 128 * 256 + tid;
        for (int s = 0; s < 128; ++s) a += sP[s] * base[s * 256];
        sEnc[tid] = a;
    }
    __syncthreads();

    if (tid < 3) {
        float z = b_out[tid];
        const float4* wv = (const float4*)(W_out + tid * 256);
        const float4* ev = (const float4*)sEnc;
        #pragma unroll 8
        for (int h = 0; h < 64; ++h) {
            float4 e4 = ev[h], w4 = wv[h];
            z += e4.x * w4.x + e4.y * w4.y + e4.z * w4.z + e4.w * w4.w;
        }
        sZ[tid] = z;
    }
    __syncthreads();
    if (tid < 3) {
        float mx = fmaxf(sZ[0], fmaxf(sZ[1], sZ[2]));
        float lse = mx + logf(expf(sZ[0] - mx) + expf(sZ[1] - mx) + expf(sZ[2] - mx));
        out[b * 3 + tid] = sZ[tid] - lse;
    }
    if (tid < 128) out[192 + b * 128 + tid] = sP[tid];
}

// ============================================================================
extern "C" void kernel_launch(void* const* d_in, const int* in_sizes, int n_in,
                              void* d_out, int out_size)
{
    const int*   inputs   = (const int*)d_in[0];
    const int*   triples  = (const int*)d_in[1];
    const int*   lengths  = (const int*)d_in[2];
    const int*   id2      = (const int*)d_in[3];
    const float* word_emb = (const float*)d_in[4];
    const float* ent_emb  = (const float*)d_in[5];
    const float* rel_emb  = (const float*)d_in[6];
    const float* W_ent    = (const float*)d_in[7];
    const float* w_ih     = (const float*)d_in[8];
    const float* w_hh     = (const float*)d_in[9];
    const float* b_ih     = (const float*)d_in[10];
    const float* b_hh     = (const float*)d_in[11];
    const float* W_att    = (const float*)d_in[12];
    const float* b_att    = (const float*)d_in[13];
    const float* W_out    = (const float*)d_in[14];
    const float* b_out    = (const float*)d_in[15];
    float* out = (float*)d_out;

    cudaFuncSetAttribute(k_token, cudaFuncAttributeMaxDynamicSharedMemorySize, TOK_SMEM);

    k_tanh_rel<<<(50000 + 255) / 256, 256>>>(rel_emb);
    k_token<<<148, 512, TOK_SMEM>>>(inputs, triples, id2, word_emb, ent_emb, W_ent);
    dim3 g2(16, 64);
    k_mma_x<<<g2, 256>>>(w_ih, b_ih, b_hh);
    k_lstm<<<128, 256>>>(w_hh, lengths);
    k_final<<<64, 256>>>(W_att, b_att, W_out, b_out, out);
}

// round 17
// speedup vs baseline: 1.0274x; 1.0274x over previous
#include <cuda_runtime.h>
#include <math.h>
#include <stdint.h>

// ---------------- device scratch ----------------
__device__ __align__(16) float g_trel[500 * 100];
__device__ __align__(16) float g_tin[8192 * 500];
__device__ __align__(16) float g_xp[8192 * 1024];
__device__ __align__(16) float g_outseq[8192 * 256];

// ---------------- helpers ----------------
__device__ __forceinline__ unsigned smem_u32(const void* p) {
    return (unsigned)__cvta_generic_to_shared(p);
}
__device__ __forceinline__ void cpa16(unsigned dst, const void* src) {
    asm volatile("cp.async.cg.shared.global [%0], [%1], 16;\n" :: "r"(dst), "l"(src));
}
#define CPA_COMMIT() asm volatile("cp.async.commit_group;\n")
template <int N> __device__ __forceinline__ void cpa_wait() {
    asm volatile("cp.async.wait_group %0;\n" :: "n"(N));
}
#define FMA2(acc, h, w) \
    asm("fma.rn.f32x2 %0, %1, %2, %0;" : "+l"(acc) : "l"(h), "l"(w))
#define UNPACK2(lo, hi, src) \
    asm("mov.b64 {%0, %1}, %2;" : "=f"(lo), "=f"(hi) : "l"(src))
#define PACKF2(dst, a, b) \
    asm("mov.b64 %0, {%1, %2};" : "=l"(dst) : "f"(a), "f"(b))
#define CLUSTER_ARRIVE() asm volatile("barrier.cluster.arrive.aligned;" ::: "memory")
#define CLUSTER_WAIT()   asm volatile("barrier.cluster.wait.aligned;" ::: "memory")

__device__ __forceinline__ float fast_sigmoid(float x) {
    return __fdividef(1.f, 1.f + __expf(-x));
}
__device__ __forceinline__ float fast_tanh(float x) {
    float e = __expf(2.f * x);
    return 1.f - __fdividef(2.f, e + 1.f);
}
__device__ __forceinline__ uint32_t f2tf(float x) {
    uint32_t r;
    asm("cvt.rna.tf32.f32 %0, %1;" : "=r"(r) : "f"(x));
    return r;
}
#define MMA_TF32(c, a, b) \
    asm volatile("mma.sync.aligned.m16n8k8.row.col.f32.tf32.tf32.f32 " \
        "{%0,%1,%2,%3}, {%4,%5,%6,%7}, {%8,%9}, {%0,%1,%2,%3};" \
        : "+f"((c)[0]), "+f"((c)[1]), "+f"((c)[2]), "+f"((c)[3]) \
        : "r"((a)[0]), "r"((a)[1]), "r"((a)[2]), "r"((a)[3]), \
          "r"((b)[0]), "r"((b)[1]))

// ============================================================================
// K0: precompute tanh(rel_emb)
// ============================================================================
__global__ void k_tanh_rel(const float* __restrict__ rel) {
    int i = blockIdx.x * 256 + threadIdx.x;
    if (i < 500 * 100) g_trel[i] = tanhf(rel[i]);
}

// ============================================================================
// K1: graph attention v5 — TWO tokens per iteration (28 iters of pairs).
// Warps 0-6: token A MMA (m32 n16 k200 tf32); warps 7-13: token B MMA;
// warps 14/15: word-embedding copies for A/B. Reduce/softmax/graph-embed
// sections process both tokens in parallel. Pair-granular cp.async staging,
// depth 2 pairs over 4 buffers.
// smem floats:
//   sW    100*204 = 20400  @ 0       (tf32 bits after prologue)
//   sHT   4*32*204 = 26112 @ 20400
//   sE    64               @ 46512
//   sPART 512              @ 46576
//   sIdx  5376 ints        @ 47088
//   sVal  56 ints          @ 52464
// total 52520 floats = 210080 B
// ============================================================================
#define TPC       56
#define TOK_SW    0
#define TOK_SHT   20400
#define TOK_SE    46512
#define TOK_SPART 46576
#define TOK_SIDX  47088
#define TOK_SVAL  52464
#define TOK_SMEM  (52520 * 4)

// stage BOTH tokens of pair ip into buffers 2*(ip&1), 2*(ip&1)+1
__device__ __forceinline__ void tok_stage_pair(float* sm, int ip, int tok0,
                                               const float* ent_emb) {
    const int bufA = 2 * (ip & 1);
    for (int i = threadIdx.x; i < 3200; i += 512) {
        int tk = i >> 11;                 // 0: first 2048? no — split evenly
        // i in [0,1600): token A; [1600,3200): token B
        tk = (i < 1600) ? 0 : 1;
        int token = tok0 + 2 * ip + tk;
        if (token >= 8192) continue;
        int r = (i < 1600) ? i : (i - 1600);
        int t = r / 50, j = r - t * 50;
        const int* idx = (const int*)(sm + TOK_SIDX) + (2 * ip + tk) * 96;
        int ent = (j < 25) ? idx[t * 3] : idx[t * 3 + 1];
        int jj = (j < 25) ? j : (j - 25);
        int dstf = t * 204 + ((j < 25) ? (j * 4) : (100 + jj * 4));
        float* sHT = sm + TOK_SHT + (bufA + tk) * 32 * 204;
        cpa16(smem_u32(sHT + dstf), ent_emb + (size_t)ent * 100 + jj * 4);
    }
}

__global__ void __launch_bounds__(512, 1)
k_token(const int* __restrict__ inputs, const int* __restrict__ triples,
        const int* __restrict__ id2, const float* __restrict__ word_emb,
        const float* __restrict__ ent_emb, const float* __restrict__ W_ent)
{
    extern __shared__ float sm[];
    const int tid = threadIdx.x;
    const int tok0 = blockIdx.x * TPC;
    int* sIdx = (int*)(sm + TOK_SIDX);
    int* sVal = (int*)(sm + TOK_SVAL);

    // prologue: indices for 56 tokens (1344 cp16 = 5376 ints) + W_ent
    for (int i = tid; i < 1344; i += 512) {
        if (tok0 + i / 24 < 8192)
            cpa16(smem_u32(sIdx) + i * 16, triples + (size_t)tok0 * 96 + i * 4);
    }
    for (int i = tid; i < 5000; i += 512) {
        int d = i / 50, j = i - d * 50;
        cpa16(smem_u32(sm + TOK_SW + d * 204 + j * 4), W_ent + d * 200 + j * 4);
    }
    CPA_COMMIT();
    cpa_wait<0>();
    __syncthreads();

    // convert sW to tf32 bit patterns (reused 56 tokens)
    for (int i = tid; i < 20000; i += 512) {
        int d = i / 200, j = i - d * 200;
        ((uint32_t*)sm)[TOK_SW + d * 204 + j] = f2tf(sm[TOK_SW + d * 204 + j]);
    }

    // per-token valid flags
    {
        int w = tid >> 5, lane = tid & 31;
        for (int it = w; it < TPC; it += 16) {
            int token = tok0 + it;
            int v = (token < 8192) ? id2[(size_t)token * 32 + lane] : -1;
            unsigned m = __ballot_sync(0xffffffffu, v != -1);
            if (lane == 0) sVal[it] = (m != 0u);
        }
    }
    __syncthreads();

    // prime: pair 0 in flight
    tok_stage_pair(sm, 0, tok0, ent_emb); CPA_COMMIT();

    const int warp = tid >> 5;
    const int lane = tid & 31;
    const int g  = lane >> 2;        // 0..7
    const int tg = lane & 3;         // 0..3
    const int wslice = (warp < 7) ? warp : (warp - 7);   // n-slice for MMA warps
    const int wtk    = (warp < 7) ? 0 : 1;               // token of this MMA warp

    for (int ip = 0; ip < TPC / 2; ++ip) {
        if (ip + 1 < TPC / 2) {
            tok_stage_pair(sm, ip + 1, tok0, ent_emb);
            CPA_COMMIT();
            cpa_wait<1>();
        } else {
            cpa_wait<0>();
        }
        __syncthreads();

        const int bufA = 2 * (ip & 1);
        const int tokA = tok0 + 2 * ip;
        const bool tvA = (tokA < 8192);
        const bool tvB = (tokA + 1 < 8192);

        if (warp < 14) {
            const bool tv = wtk ? tvB : tvA;
            if (tv) {
                const float* sHT = sm + TOK_SHT + (bufA + wtk) * 32 * 204;
                // prefetch trel (hidden under MMA)
                const int* idx = sIdx + (2 * ip + wtk) * 96;
                int c0 = wslice * 16 + tg * 2;
                int cols[4] = {c0, c0 + 1, c0 + 8, c0 + 9};
                float T[4][4];
                #pragma unroll
                for (int rr = 0; rr < 4; ++rr) {
                    int rl = idx[(g + rr * 8) * 3 + 2];
                    #pragma unroll
                    for (int cc = 0; cc < 4; ++cc)
                        T[rr][cc] = (cols[cc] < 100) ? __ldg(g_trel + rl * 100 + cols[cc]) : 0.f;
                }

                float acc[2][2][4];
                #pragma unroll
                for (int mt = 0; mt < 2; ++mt)
                    #pragma unroll
                    for (int nt = 0; nt < 2; ++nt)
                        #pragma unroll
                        for (int c = 0; c < 4; ++c) acc[mt][nt][c] = 0.f;

                const float* Afrag = sHT + g * 204 + tg;
                const uint32_t* B0 = (const uint32_t*)(sm + TOK_SW) + (wslice * 16 + g) * 204 + tg;
                const uint32_t* B1 = (const uint32_t*)(sm + TOK_SW) + (wslice * 16 + 8 + g) * 204 + tg;
                const bool okn0 = (wslice * 16 + g) < 100;
                const bool okn1 = (wslice * 16 + 8 + g) < 100;

                #pragma unroll 5
                for (int ks = 0; ks < 25; ++ks) {
                    int ko = ks * 8;
                    uint32_t a[2][4], b0[2], b1[2];
                    #pragma unroll
                    for (int mt = 0; mt < 2; ++mt) {
                        const float* p = Afrag + mt * (16 * 204) + ko;
                        a[mt][0] = f2tf(p[0]);
                        a[mt][1] = f2tf(p[8 * 204]);
                        a[mt][2] = f2tf(p[4]);
                        a[mt][3] = f2tf(p[8 * 204 + 4]);
                    }
                    b0[0] = okn0 ? B0[ko] : 0u;  b0[1] = okn0 ? B0[ko + 4] : 0u;
                    b1[0] = okn1 ? B1[ko] : 0u;  b1[1] = okn1 ? B1[ko + 4] : 0u;
                    MMA_TF32(acc[0][0], a[0], b0);
                    MMA_TF32(acc[0][1], a[0], b1);
                    MMA_TF32(acc[1][0], a[1], b0);
                    MMA_TF32(acc[1][1], a[1], b1);
                }

                float pr[4];
                pr[0] = fast_tanh(acc[0][0][0]) * T[0][0] + fast_tanh(acc[0][0][1]) * T[0][1]
                      + fast_tanh(acc[0][1][0]) * T[0][2] + fast_tanh(acc[0][1][1]) * T[0][3];
                pr[1] = fast_tanh(acc[0][0][2]) * T[1][0] + fast_tanh(acc[0][0][3]) * T[1][1]
                      + fast_tanh(acc[0][1][2]) * T[1][2] + fast_tanh(acc[0][1][3]) * T[1][3];
                pr[2] = fast_tanh(acc[1][0][0]) * T[2][0] + fast_tanh(acc[1][0][1]) * T[2][1]
                      + fast_tanh(acc[1][1][0]) * T[2][2] + fast_tanh(acc[1][1][1]) * T[2][3];
                pr[3] = fast_tanh(acc[1][0][2]) * T[3][0] + fast_tanh(acc[1][0][3]) * T[3][1]
                      + fast_tanh(acc[1][1][2]) * T[3][2] + fast_tanh(acc[1][1][3]) * T[3][3];
                #pragma unroll
                for (int rr = 0; rr < 4; ++rr) {
                    pr[rr] += __shfl_xor_sync(0xffffffffu, pr[rr], 1);
                    pr[rr] += __shfl_xor_sync(0xffffffffu, pr[rr], 2);
                }
                if (tg == 0) {
                    #pragma unroll
                    for (int rr = 0; rr < 4; ++rr)
                        sm[TOK_SPART + wtk * 256 + (g + rr * 8) * 8 + wslice] = pr[rr];
                }
            }
        } else {
            // warps 14/15: word-embedding copy for tokens A/B
            int tk = warp - 14;
            int token = tokA + tk;
            if (token < 8192) {
                const int widx = inputs[token];
                const float2* wsrc = (const float2*)(word_emb + (size_t)widx * 300);
                float2* wdst = (float2*)(g_tin + (size_t)token * 500);
                for (int j = lane; j < 150; j += 32) wdst[j] = wsrc[j];
            }
        }
        __syncthreads();

        // reduce 7 warp-partials per row, both tokens (512 threads)
        {
            int tk = tid >> 8;              // 0/1
            int t = (tid >> 3) & 31;
            int l = tid & 7;
            float v = (l < 7) ? sm[TOK_SPART + tk * 256 + t * 8 + l] : 0.f;
            v += __shfl_xor_sync(0xffffffffu, v, 4);
            v += __shfl_xor_sync(0xffffffffu, v, 2);
            v += __shfl_xor_sync(0xffffffffu, v, 1);
            if (l == 0) sm[TOK_SE + tk * 32 + t] = v;
        }
        __syncthreads();

        // softmax: warp 0 -> token A, warp 1 -> token B
        if (warp < 2) {
            bool tv = warp ? tvB : tvA;
            if (tv) {
                float v = sm[TOK_SE + warp * 32 + lane];
                float m = v;
                #pragma unroll
                for (int o = 16; o; o >>= 1) m = fmaxf(m, __shfl_xor_sync(0xffffffffu, m, o));
                float e = __expf(v - m);
                float z = e;
                #pragma unroll
                for (int o = 16; o; o >>= 1) z += __shfl_xor_sync(0xffffffffu, z, o);
                sm[TOK_SE + warp * 32 + lane] = e / z;
            }
        }
        __syncthreads();

        // graph embed: threads 0-199 -> A, 256-455 -> B
        {
            int tk = tid >> 8;
            int col = tid & 255;
            bool tv = tk ? tvB : tvA;
            if (col < 200 && tv) {
                const float* sHT = sm + TOK_SHT + (bufA + tk) * 32 * 204;
                const float* sE = sm + TOK_SE + tk * 32;
                float ge = 0.f;
                #pragma unroll 8
                for (int t = 0; t < 32; ++t) ge += sE[t] * sHT[t * 204 + col];
                int token = tokA + tk;
                g_tin[(size_t)token * 500 + 300 + col] = sVal[2 * ip + tk] ? ge : 0.f;
            }
        }
        __syncthreads();
    }
}

// ============================================================================
// K2: tf32 tensor-core GEMM (round-10 proven, FROZEN).
// ============================================================================
__global__ void __launch_bounds__(256)
k_mma_x(const float* __restrict__ wih, const float* __restrict__ bih,
        const float* __restrict__ bhh)
{
    __shared__ float As[128 * 36];
    __shared__ float Bs[64 * 36];

    const int tid  = threadIdx.x;
    const int lane = tid & 31;
    const int warp = tid >> 5;
    const int wm = warp >> 1;
    const int wn = warp & 1;
    const int g  = lane >> 2;
    const int tg = lane & 3;
    const int m0 = blockIdx.y * 128;
    const int n0 = blockIdx.x * 64;

    const int arow_i = tid >> 1;
    const int ahalf  = (tid & 1) * 16;
    const float* arow = g_tin + (size_t)(m0 + arow_i) * 500;
    const int brow_i = tid >> 2;
    const int bq     = (tid & 3) * 8;
    const float* brow = wih + (size_t)(n0 + brow_i) * 500;

    float acc[2][4][4];
    #pragma unroll
    for (int mt = 0; mt < 2; ++mt)
        #pragma unroll
        for (int nt = 0; nt < 4; ++nt)
            #pragma unroll
            for (int c = 0; c < 4; ++c) acc[mt][nt][c] = 0.f;

    float4 av[4], bv[2];
    #pragma unroll
    for (int j = 0; j < 4; ++j) {
        int k = ahalf + j * 4;
        av[j] = (k < 500) ? *(const float4*)(arow + k) : make_float4(0.f,0.f,0.f,0.f);
    }
    #pragma unroll
    for (int j = 0; j < 2; ++j) {
        int k = bq + j * 4;
        bv[j] = (k < 500) ? *(const float4*)(brow + k) : make_float4(0.f,0.f,0.f,0.f);
    }

    const float* Afrag = As + (wm * 32 + g) * 36 + tg;
    const float* Bfrag = Bs + (wn * 32 + g) * 36 + tg;

    for (int kt = 0; kt < 16; ++kt) {
        #pragma unroll
        for (int j = 0; j < 4; ++j)
            *(float4*)&As[arow_i * 36 + ahalf + j * 4] = av[j];
        #pragma unroll
        for (int j = 0; j < 2; ++j)
            *(float4*)&Bs[brow_i * 36 + bq + j * 4] = bv[j];
        __syncthreads();

        if (kt < 15) {
            int kb = (kt + 1) * 32;
            #pragma unroll
            for (int j = 0; j < 4; ++j) {
                int k = kb + ahalf + j * 4;
                av[j] = (k < 500) ? *(const float4*)(arow + k) : make_float4(0.f,0.f,0.f,0.f);
            }
            #pragma unroll
            for (int j = 0; j < 2; ++j) {
                int k = kb + bq + j * 4;
                bv[j] = (k < 500) ? *(const float4*)(brow + k) : make_float4(0.f,0.f,0.f,0.f);
            }
        }

        #pragma unroll
        for (int k8 = 0; k8 < 4; ++k8) {
            int ko = k8 * 8;
            uint32_t a[2][4], b[4][2];
            #pragma unroll
            for (int mt = 0; mt < 2; ++mt) {
                const float* p = Afrag + mt * (16 * 36) + ko;
                a[mt][0] = f2tf(p[0]);
                a[mt][1] = f2tf(p[8 * 36]);
                a[mt][2] = f2tf(p[4]);
                a[mt][3] = f2tf(p[8 * 36 + 4]);
            }
            #pragma unroll
            for (int nt = 0; nt < 4; ++nt) {
                const float* q = Bfrag + nt * (8 * 36) + ko;
                b[nt][0] = f2tf(q[0]);
                b[nt][1] = f2tf(q[4]);
            }
            #pragma unroll
            for (int mt = 0; mt < 2; ++mt)
                #pragma unroll
                for (int nt = 0; nt < 4; ++nt)
                    MMA_TF32(acc[mt][nt], a[mt], b[nt]);
        }
        __syncthreads();
    }

    #pragma unroll
    for (int nt = 0; nt < 4; ++nt) {
        int c = n0 + wn * 32 + nt * 8 + tg * 2;
        float b0 = bih[c] + bhh[c];
        float b1 = bih[c + 1] + bhh[c + 1];
        #pragma unroll
        for (int mt = 0; mt < 2; ++mt) {
            int r = m0 + wm * 32 + mt * 16 + g;
            float2 o0 = make_float2(acc[mt][nt][0] + b0, acc[mt][nt][1] + b1);
            float2 o1 = make_float2(acc[mt][nt][2] + b0, acc[mt][nt][3] + b1);
            *(float2*)(g_xp + (size_t)r * 1024 + c) = o0;
            *(float2*)(g_xp + (size_t)(r + 8) * 1024 + c) = o1;
        }
    }
}

// ============================================================================
// K3: cluster LSTM (round-8 design, FROZEN). 16 clusters x 8 CTAs x 256 thr.
// ============================================================================
__global__ void __launch_bounds__(256, 1) __cluster_dims__(8, 1, 1)
k_lstm(const float* __restrict__ whh, const int* __restrict__ lengths)
{
    __shared__ __align__(16) float sH[2][4][256];   // [buf][batch][k swizzled]

    const int tid  = threadIdx.x;
    const int rank = blockIdx.x & 7;
    const int cid  = blockIdx.x >> 3;
    const int b0g  = cid * 4;

    const int hc_l = tid >> 3;          // 0..31
    const int ks   = tid & 7;           // k-slice
    const int k_g  = rank * 32 + hc_l;

    unsigned long long w[4][16];
    #pragma unroll
    for (int g = 0; g < 4; ++g) {
        const float4* p = (const float4*)(whh + ((size_t)(g * 256 + k_g)) * 256 + ks * 32);
        #pragma unroll
        for (int j = 0; j < 8; ++j) {
            float4 v = __ldg(p + j);
            PACKF2(w[g][2*j],   v.x, v.y);
            PACKF2(w[g][2*j+1], v.z, v.w);
        }
    }

    for (int i = tid; i < 2 * 4 * 256; i += 256) (&sH[0][0][0])[i] = 0.f;

    const int ab = ks;                  // batch for activation lanes (ks<4)
    float cst = 0.f;
    int mylen = 0;
    if (ks < 4) mylen = lengths[b0g + ab];
    const int sw_idx = k_g ^ (rank << 2);

    __syncthreads();
    CLUSTER_ARRIVE(); CLUSTER_WAIT();

    int buf = 0;
    for (int s = 0; s < 128; ++s) {
        float xg0 = 0.f, xg1 = 0.f, xg2 = 0.f, xg3 = 0.f;
        if (ks < 4) {
            const float* xp = g_xp + ((size_t)((b0g + ab) * 128 + s)) * 1024 + k_g;
            xg0 = __ldg(xp);       xg1 = __ldg(xp + 256);
            xg2 = __ldg(xp + 512); xg3 = __ldg(xp + 768);
        }

        unsigned long long acc[4][4];
        #pragma unroll
        for (int g = 0; g < 4; ++g)
            #pragma unroll
            for (int b = 0; b < 4; ++b) acc[g][b] = 0ull;

        const float* hb = &sH[buf][0][0];
        #pragma unroll
        for (int i = 0; i < 8; ++i) {
            int off = (ks * 32 + i * 4) ^ (ks << 2);
            ulonglong2 x0 = *(const ulonglong2*)(hb + 0   + off);
            ulonglong2 x1 = *(const ulonglong2*)(hb + 256 + off);
            ulonglong2 x2 = *(const ulonglong2*)(hb + 512 + off);
            ulonglong2 x3 = *(const ulonglong2*)(hb + 768 + off);
            #pragma unroll
            for (int g = 0; g < 4; ++g) {
                FMA2(acc[g][0], x0.x, w[g][2*i]); FMA2(acc[g][0], x0.y, w[g][2*i+1]);
                FMA2(acc[g][1], x1.x, w[g][2*i]); FMA2(acc[g][1], x1.y, w[g][2*i+1]);
                FMA2(acc[g][2], x2.x, w[g][2*i]); FMA2(acc[g][2], x2.y, w[g][2*i+1]);
                FMA2(acc[g][3], x3.x, w[g][2*i]); FMA2(acc[g][3], x3.y, w[g][2*i+1]);
            }
        }

        float r[4][4];
        #pragma unroll
        for (int g = 0; g < 4; ++g)
            #pragma unroll
            for (int b = 0; b < 4; ++b) {
                float lo, hi;
                UNPACK2(lo, hi, acc[g][b]);
                r[g][b] = lo + hi;
            }
        #pragma unroll
        for (int o = 1; o < 8; o <<= 1)
            #pragma unroll
            for (int g = 0; g < 4; ++g)
                #pragma unroll
                for (int b = 0; b < 4; ++b)
                    r[g][b] += __shfl_xor_sync(0xffffffffu, r[g][b], o);

        if (ks < 4) {
            float gi = xg0 + r[0][ab];
            float gf = xg1 + r[1][ab];
            float gg = xg2 + r[2][ab];
            float go = xg3 + r[3][ab];
            float si = fast_sigmoid(gi);
            float sf = fast_sigmoid(gf);
            float so = fast_sigmoid(go);
            cst = sf * cst + si * fast_tanh(gg);
            float hv = so * fast_tanh(cst);
            g_outseq[((size_t)((b0g + ab) * 128 + s)) * 256 + k_g] =
                (s < mylen) ? hv : 0.f;
            unsigned laddr = smem_u32(&sH[buf ^ 1][ab][sw_idx]);
            #pragma unroll
            for (int rr = 0; rr < 8; ++rr) {
                unsigned raddr;
                asm("mapa.shared::cluster.u32 %0, %1, %2;" : "=r"(raddr) : "r"(laddr), "r"(rr));
                asm volatile("st.shared::cluster.f32 [%0], %1;" :: "r"(raddr), "f"(hv));
            }
        }
        CLUSTER_ARRIVE();
        CLUSTER_WAIT();
        buf ^= 1;
    }
}

// ============================================================================
// K4: attention pool + classifier (float4 dots, 16B-aligned shared).
// out = [ log_probs (64*3) | p (64*128) ]
// ============================================================================
__global__ void __launch_bounds__(256)
k_final(const float* __restrict__ W_att, const float* __restrict__ b_att,
        const float* __restrict__ W_out, const float* __restrict__ b_out,
        float* __restrict__ out)
{
    __shared__ __align__(16) float sLog[128];
    __shared__ __align__(16) float sP[128];
    __shared__ __align__(16) float sEnc[256];
    __shared__ __align__(16) float sZ[4];
    const int tid = threadIdx.x;
    const int b = blockIdx.x;

    if (tid < 128) {
        const float4* o = (const float4*)(g_outseq + (size_t)(b * 128 + tid) * 256);
        const float4* wv = (const float4*)W_att;
        float a = 0.f;
        #pragma unroll 8
        for (int h = 0; h < 64; ++h) {
            float4 ov = o[h], w4 = wv[h];
            a += ov.x * w4.x + ov.y * w4.y + ov.z * w4.z + ov.w * w4.w;
        }
        sLog[tid] = a + b_att[0];
    }
    __syncthreads();

    if (tid < 32) {
        float lv[4], mk[4];
        #pragma unroll
        for (int i = 0; i < 4; ++i) {
            float x = sLog[tid + 32 * i];
            mk[i] = (x != 0.f) ? 1.f : 0.f;
            lv[i] = x * mk[i];
        }
        float mx = fmaxf(fmaxf(lv[0], lv[1]), fmaxf(lv[2], lv[3]));
        #pragma unroll
        for (int o = 16; o; o >>= 1) mx = fmaxf(mx, __shfl_xor_sync(0xffffffffu, mx, o));
        float e[4], den = 0.f;
        #pragma unroll
        for (int i = 0; i < 4; ++i) { e[i] = __expf(lv[i] - mx); den += e[i]; }
        #pragma unroll
        for (int o = 16; o; o >>= 1) den += __shfl_xor_sync(0xffffffffu, den, o);
        float pv[4], s2 = 0.f;
        #pragma unroll
        for (int i = 0; i < 4; ++i) { pv[i] = e[i] / den * mk[i]; s2 += pv[i]; }
        #pragma unroll
        for (int o = 16; o; o >>= 1) s2 += __shfl_xor_sync(0xffffffffu, s2, o);
        float inv = 1.f / (s2 + 1e-13f);
        #pragma unroll
        for (int i = 0; i < 4; ++i) sP[tid + 32 * i] = pv[i] * inv;
    }
    __syncthreads();

    {
        float a = 0.f;
        const float* base = g_outseq + (size_t)b * 128 * 256 + tid;
        for (int s = 0; s < 128; ++s) a += sP[s] * base[s * 256];
        sEnc[tid] = a;
    }
    __syncthreads();

    if (tid < 3) {
        float z = b_out[tid];
        const float4* wv = (const float4*)(W_out + tid * 256);
        const float4* ev = (const float4*)sEnc;
        #pragma unroll 8
        for (int h = 0; h < 64; ++h) {
            float4 e4 = ev[h], w4 = wv[h];
            z += e4.x * w4.x + e4.y * w4.y + e4.z * w4.z + e4.w * w4.w;
        }
        sZ[tid] = z;
    }
    __syncthreads();
    if (tid < 3) {
        float mx = fmaxf(sZ[0], fmaxf(sZ[1], sZ[2]));
        float lse = mx + logf(expf(sZ[0] - mx) + expf(sZ[1] - mx) + expf(sZ[2] - mx));
        out[b * 3 + tid] = sZ[tid] - lse;
    }
    if (tid < 128) out[192 + b * 128 + tid] = sP[tid];
}

// ============================================================================
extern "C" void kernel_launch(void* const* d_in, const int* in_sizes, int n_in,
                              void* d_out, int out_size)
{
    const int*   inputs   = (const int*)d_in[0];
    const int*   triples  = (const int*)d_in[1];
    const int*   lengths  = (const int*)d_in[2];
    const int*   id2      = (const int*)d_in[3];
    const float* word_emb = (const float*)d_in[4];
    const float* ent_emb  = (const float*)d_in[5];
    const float* rel_emb  = (const float*)d_in[6];
    const float* W_ent    = (const float*)d_in[7];
    const float* w_ih     = (const float*)d_in[8];
    const float* w_hh     = (const float*)d_in[9];
    const float* b_ih     = (const float*)d_in[10];
    const float* b_hh     = (const float*)d_in[11];
    const float* W_att    = (const float*)d_in[12];
    const float* b_att    = (const float*)d_in[13];
    const float* W_out    = (const float*)d_in[14];
    const float* b_out    = (const float*)d_in[15];
    float* out = (float*)d_out;

    cudaFuncSetAttribute(k_token, cudaFuncAttributeMaxDynamicSharedMemorySize, TOK_SMEM);

    k_tanh_rel<<<(50000 + 255) / 256, 256>>>(rel_emb);
    k_token<<<148, 512, TOK_SMEM>>>(inputs, triples, id2, word_emb, ent_emb, W_ent);
    dim3 g2(16, 64);
    k_mma_x<<<g2, 256>>>(w_ih, b_ih, b_hh);
    k_lstm<<<128, 256>>>(w_hh, lengths);
    k_final<<<64, 256>>>(W_att, b_att, W_out, b_out, out);
}